// round 6
// baseline (speedup 1.0000x reference)
#include <cuda_runtime.h>
#include <math.h>

#define NP 512
#define GD 64
#define K2STRIDE (4224*64)
#define CB_BK 32
#define CB_NKS 64
#define ENT_PER_M 4096   // worst case: 512 pairs * 8 taps

// ---------------- scratch (device globals; no allocations) ----------------
__device__ float d_h0[NP*68];                 // layer-0 features, stride 68
__device__ float d_bufA[NP*64];               // ping-pong layer outputs
__device__ float d_bufB[NP*64];
__device__ float d_t[NP*GD*66];               // t[m][g*ci + i]
__device__ int   d_goff[NP*GD];               // CSR: absolute offset of (m,g) entry list
__device__ int   d_gcnt[NP*GD];               // CSR: entry count per (m,g)
__device__ uint2 d_gent[NP*ENT_PER_M];        // CSR entries: {n, weight}
__device__ float d_K2[5*K2STRIDE];            // K rearranged: [(g*ci+i)][o] per layer

// ---------------- prep 1: layer-0 features ----------------
__global__ void prep_feats_kernel(const float* __restrict__ v, const float* __restrict__ other)
{
    int stride = gridDim.x * blockDim.x;
    for (int e = blockIdx.x * blockDim.x + threadIdx.x; e < NP*68; e += stride) {
        int n = e / 68, i = e - n*68;
        float val;
        if (i == 0)       val = 1.0f;
        else if (i < 4)   val = v[n*3 + (i-1)];
        else if (i < 66)  val = other[n*62 + (i-4)];
        else              val = 0.0f;
        d_h0[e] = val;
    }
}

// ---------------- prep 2: rearranged conv kernels ----------------
__global__ void prep_k2_kernel(const float* __restrict__ k0, const float* __restrict__ k1,
                               const float* __restrict__ k2, const float* __restrict__ k3,
                               const float* __restrict__ k4)
{
    int l = blockIdx.y;
    const float* src = (l==0)?k0 : (l==1)?k1 : (l==2)?k2 : (l==3)?k3 : k4;
    int ci = (l==0) ? 66 : 64;
    int co = (l==0) ? 32 : ((l==4) ? 6 : 64);
    int tot = GD*ci*co;
    float* dst = d_K2 + l*K2STRIDE;
    int stride = gridDim.x * blockDim.x;
    for (int e = blockIdx.x * blockDim.x + threadIdx.x; e < tot; e += stride) {
        int o  = e % co;
        int t2 = e / co;
        int i  = t2 % ci;
        int g  = t2 / ci;
        dst[e] = src[(o*ci + i)*GD + g];
    }
}

// ---------------- geometry + CSR build (layer-invariant, built once) ----------------
__global__ void __launch_bounds__(256) geom_kernel(const float* __restrict__ p,
                                                   const float* __restrict__ mask)
{
    __shared__ float s_w8[NP][8];
    __shared__ unsigned long long s_gp[NP];
    __shared__ unsigned short s_n[NP];
    __shared__ int s_cnt[8];
    __shared__ int s_gc[64];
    __shared__ int s_go[64];

    int m = blockIdx.x;
    int tid = threadIdx.x;
    int lane = tid & 31, warp = tid >> 5;
    float pmx = p[m*3+0], pmy = p[m*3+1], pmz = p[m*3+2];
    const float INV_R = 1.0f/40.0f;
    const float C4PI  = 1.2732395447351628f;
    int cnt = 0;
    int cbase = warp*64;
    #pragma unroll
    for (int round = 0; round < 2; round++) {
        int n = cbase + round*32 + lane;
        float rx = (p[n*3+0]-pmx)*INV_R;
        float ry = (p[n*3+1]-pmy)*INV_R;
        float rz = (p[n*3+2]-pmz)*INV_R;
        float r2 = rx*rx + ry*ry + rz*rz;
        float mk = mask[n];
        float t1 = 1.0f - r2;
        bool active = (t1 > 0.0f) && (mk != 0.0f);
        float w8[8];
        unsigned long long gp = 0ull;
        if (active) {
            float att = t1*t1*t1*mk;
            float r = sqrtf(rx*rx + ry*ry + 1e-9f);
            float xs, ys;
            if (rx == 0.0f && ry == 0.0f) { xs = 0.0f; ys = 0.0f; }
            else if (fabsf(ry) <= fabsf(rx)) {
                float s = copysignf(r, rx);
                xs = s;
                ys = C4PI * s * atanf(ry / rx);
            } else {
                float s = copysignf(r, ry);
                ys = s;
                xs = C4PI * s * atanf(rx / ry);
            }
            float zs = rz;
            float cz = 2.0f*zs + 1.5f, cy = 2.0f*ys + 1.5f, cx = 2.0f*xs + 1.5f;
            float fz0 = floorf(cz), fy0 = floorf(cy), fx0 = floorf(cx);
            int iz = (int)fz0, iy = (int)fy0, ix = (int)fx0;
            float fz = cz - fz0, fy = cy - fy0, fx = cx - fx0;
            float wz[2] = {1.0f-fz, fz};
            float wy[2] = {1.0f-fy, fy};
            float wx[2] = {1.0f-fx, fx};
            #pragma unroll
            for (int dz = 0; dz < 2; dz++)
            #pragma unroll
            for (int dy = 0; dy < 2; dy++)
            #pragma unroll
            for (int dx = 0; dx < 2; dx++) {
                int k = dz*4 + dy*2 + dx;
                int z = iz+dz, y = iy+dy, x = ix+dx;
                bool valid = ((unsigned)z < 4u) && ((unsigned)y < 4u) && ((unsigned)x < 4u);
                float w = valid ? (wz[dz]*wy[dy]*wx[dx]*att) : 0.0f;
                int g = valid ? (z*16 + y*4 + x) : 64;
                w8[k] = w;
                gp |= ((unsigned long long)(unsigned)g) << (8*k);
            }
        }
        unsigned bal = __ballot_sync(0xffffffffu, active);
        int pos = cnt + __popc(bal & ((1u << lane) - 1u));
        if (active) {
            int slot = cbase + pos;
            s_n[slot]  = (unsigned short)n;
            s_gp[slot] = gp;
            #pragma unroll
            for (int k = 0; k < 8; k++) s_w8[slot][k] = w8[k];
        }
        cnt += __popc(bal);
    }
    if (lane == 0) s_cnt[warp] = cnt;
    __syncthreads();

    if (tid < 64) {
        int g = tid;
        int count = 0;
        for (int c = 0; c < 8; c++) {
            int cn = s_cnt[c];
            for (int j = 0; j < cn; j++) {
                unsigned long long gp = s_gp[c*64 + j];
                #pragma unroll
                for (int k = 0; k < 8; k++)
                    if ((int)((gp >> (8*k)) & 255ull) == g) count++;
            }
        }
        s_gc[g] = count;
    }
    __syncthreads();
    if (tid == 0) {
        int acc = 0;
        for (int g = 0; g < 64; g++) { s_go[g] = acc; acc += s_gc[g]; }
    }
    __syncthreads();
    if (tid < 64) {
        int g = tid;
        int pos = m*ENT_PER_M + s_go[g];
        d_goff[m*64 + g] = pos;
        d_gcnt[m*64 + g] = s_gc[g];
        for (int c = 0; c < 8; c++) {
            int cn = s_cnt[c];
            for (int j = 0; j < cn; j++) {
                int slot = c*64 + j;
                unsigned long long gp = s_gp[slot];
                #pragma unroll
                for (int k = 0; k < 8; k++) {
                    if ((int)((gp >> (8*k)) & 255ull) == g) {
                        uint2 e;
                        e.x = (unsigned)s_n[slot];
                        e.y = __float_as_uint(s_w8[slot][k]);
                        d_gent[pos] = e;
                        pos++;
                    }
                }
            }
        }
    }
}

// ---------------- kernel A: CSR gather into registers + dense tail ----------------
// 256 threads = 8 warps; warp w handles g in [8w, 8w+8), two lists at a time (MLP=4).
__global__ void __launch_bounds__(256) convA_kernel(
    int finsel, int dorelu, int ci, int fstride,
    const float* __restrict__ W, const float* __restrict__ bias,
    int outsel, float* __restrict__ dout, int mode)
{
    const float* fin = (finsel==0) ? d_h0 : (finsel==1) ? d_bufA : d_bufB;
    float* outbuf = (outsel==0) ? d_bufA : (outsel==1) ? d_bufB : dout;

    int m = blockIdx.x;
    int tid = threadIdx.x;
    int lane = tid & 31, warp = tid >> 5;
    bool extra = (ci == 66) && (lane < 2);

    #pragma unroll 1
    for (int q = 0; q < 4; q++) {
        int g0 = warp*8 + 2*q;
        int g1 = g0 + 1;
        int off0 = d_goff[m*64 + g0], c0 = d_gcnt[m*64 + g0];
        int off1 = d_goff[m*64 + g1], c1 = d_gcnt[m*64 + g1];
        const uint2* e0p = d_gent + off0;
        const uint2* e1p = d_gent + off1;
        float ax0 = 0.f, ay0 = 0.f, ae0 = 0.f;
        float ax1 = 0.f, ay1 = 0.f, ae1 = 0.f;
        int cmax = max(c0, c1);
        #pragma unroll 2
        for (int e = 0; e < cmax; e++) {
            uint2 ea = (e < c0) ? __ldg(e0p + e) : make_uint2(0u, 0u);
            uint2 eb = (e < c1) ? __ldg(e1p + e) : make_uint2(0u, 0u);
            float w0 = __uint_as_float(ea.y);
            float w1 = __uint_as_float(eb.y);
            const float* fr0 = fin + ea.x * fstride;
            const float* fr1 = fin + eb.x * fstride;
            float2 fA = *(const float2*)(fr0 + 2*lane);
            float2 fB = *(const float2*)(fr1 + 2*lane);
            if (dorelu) {
                fA.x = fmaxf(fA.x, 0.0f); fA.y = fmaxf(fA.y, 0.0f);
                fB.x = fmaxf(fB.x, 0.0f); fB.y = fmaxf(fB.y, 0.0f);
            }
            ax0 = fmaf(w0, fA.x, ax0); ay0 = fmaf(w0, fA.y, ay0);
            ax1 = fmaf(w1, fB.x, ax1); ay1 = fmaf(w1, fB.y, ay1);
            if (extra) {
                float fe0 = fr0[64 + lane];
                float fe1 = fr1[64 + lane];
                if (dorelu) { fe0 = fmaxf(fe0, 0.0f); fe1 = fmaxf(fe1, 0.0f); }
                ae0 = fmaf(w0, fe0, ae0);
                ae1 = fmaf(w1, fe1, ae1);
            }
        }
        float* tp0 = d_t + (size_t)m*(64*ci) + g0*ci;
        float* tp1 = d_t + (size_t)m*(64*ci) + g1*ci;
        tp0[2*lane] = ax0; tp0[2*lane + 1] = ay0;
        tp1[2*lane] = ax1; tp1[2*lane + 1] = ay1;
        if (extra) { tp0[64 + lane] = ae0; tp1[64 + lane] = ae1; }
    }

    // dense tail: initialize output buffer; conv part atomic-added by convB.
    if (mode == 0) {
        if (tid < 64) {
            float val = 0.0f;
            if (tid >= 32) {
                int o = tid - 32;
                float acc = bias[o];
                for (int i = 0; i < 66; i++) acc = fmaf(fin[m*68 + i], W[o*66 + i], acc);
                val = acc;
            }
            outbuf[m*64 + tid] = val;
        }
    } else if (mode == 1) {
        if (tid < 64) {
            int o = tid;
            float acc = bias[o] + fin[m*64 + o];   // residual (raw, no relu)
            for (int i = 0; i < 64; i++)
                acc = fmaf(fmaxf(fin[m*64 + i], 0.0f), W[o*64 + i], acc);
            outbuf[m*64 + o] = acc;
        }
    } else {
        if (tid < 6) {
            int o = tid;
            float acc = bias[o];
            for (int i = 0; i < 64; i++)
                acc = fmaf(fmaxf(fin[m*64 + i], 0.0f), W[o*64 + i], acc);
            outbuf[m*6 + o] = acc;
        }
    }
}

// ---------------- kernel B: k-split tiled GEMM  out[m][o] += sum_k t[m][k]*K2[k][o] --------
__global__ void __launch_bounds__(256) convB_kernel(
    int layer, int Ktot, int co, int ow, int outsel, float* __restrict__ dout)
{
    __shared__ float sA[CB_BK][68];   // [k][m]
    __shared__ float sB[CB_BK][64];   // [k][o]
    const float* K2l = d_K2 + layer*K2STRIDE;
    float* outbuf = (outsel==0) ? d_bufA : (outsel==1) ? d_bufB : dout;

    int m0 = blockIdx.x * 64;
    int tid = threadIdx.x;
    int nchunks = (Ktot + CB_BK - 1) / CB_BK;

    int mA = tid & 63;
    int kA = (tid >> 6) * 8;
    const float* tbase = d_t + (size_t)(m0 + mA) * Ktot;
    int kB = tid >> 3;
    int oB = (tid & 7) * 8;

    int tx = (tid & 15) * 4;
    int ty = (tid >> 4) * 4;

    float acc[16];
    #pragma unroll
    for (int j = 0; j < 16; j++) acc[j] = 0.0f;

    float ra[8], rb[8];

    int c = blockIdx.y;
    if (c >= nchunks) return;
    {
        int kb = c * CB_BK;
        int ka0 = kb + kA;
        if (ka0 + 7 < Ktot) {
            float4 v0 = *(const float4*)(tbase + ka0);
            float4 v1 = *(const float4*)(tbase + ka0 + 4);
            ra[0]=v0.x; ra[1]=v0.y; ra[2]=v0.z; ra[3]=v0.w;
            ra[4]=v1.x; ra[5]=v1.y; ra[6]=v1.z; ra[7]=v1.w;
        } else {
            #pragma unroll
            for (int j = 0; j < 8; j++) ra[j] = (ka0 + j < Ktot) ? tbase[ka0 + j] : 0.0f;
        }
        int kg = kb + kB;
        if (co == 64 && kg < Ktot) {
            const float* bp = K2l + (size_t)kg*64 + oB;
            float4 v0 = *(const float4*)bp;
            float4 v1 = *(const float4*)(bp + 4);
            rb[0]=v0.x; rb[1]=v0.y; rb[2]=v0.z; rb[3]=v0.w;
            rb[4]=v1.x; rb[5]=v1.y; rb[6]=v1.z; rb[7]=v1.w;
        } else {
            #pragma unroll
            for (int j = 0; j < 8; j++)
                rb[j] = (kg < Ktot && (oB + j) < co) ? K2l[(size_t)kg*co + oB + j] : 0.0f;
        }
    }

    while (c < nchunks) {
        #pragma unroll
        for (int j = 0; j < 8; j++) sA[kA + j][mA] = ra[j];
        #pragma unroll
        for (int j = 0; j < 8; j++) sB[kB][oB + j] = rb[j];
        __syncthreads();

        int cn = c + CB_NKS;
        if (cn < nchunks) {
            int kb = cn * CB_BK;
            int ka0 = kb + kA;
            if (ka0 + 7 < Ktot) {
                float4 v0 = *(const float4*)(tbase + ka0);
                float4 v1 = *(const float4*)(tbase + ka0 + 4);
                ra[0]=v0.x; ra[1]=v0.y; ra[2]=v0.z; ra[3]=v0.w;
                ra[4]=v1.x; ra[5]=v1.y; ra[6]=v1.z; ra[7]=v1.w;
            } else {
                #pragma unroll
                for (int j = 0; j < 8; j++) ra[j] = (ka0 + j < Ktot) ? tbase[ka0 + j] : 0.0f;
            }
            int kg = kb + kB;
            if (co == 64 && kg < Ktot) {
                const float* bp = K2l + (size_t)kg*64 + oB;
                float4 v0 = *(const float4*)bp;
                float4 v1 = *(const float4*)(bp + 4);
                rb[0]=v0.x; rb[1]=v0.y; rb[2]=v0.z; rb[3]=v0.w;
                rb[4]=v1.x; rb[5]=v1.y; rb[6]=v1.z; rb[7]=v1.w;
            } else {
                #pragma unroll
                for (int j = 0; j < 8; j++)
                    rb[j] = (kg < Ktot && (oB + j) < co) ? K2l[(size_t)kg*co + oB + j] : 0.0f;
            }
        }

        #pragma unroll
        for (int k = 0; k < CB_BK; k++) {
            float4 b4 = *(const float4*)&sB[k][tx];
            float4 a4 = *(const float4*)&sA[k][ty];
            acc[ 0] = fmaf(a4.x, b4.x, acc[ 0]);
            acc[ 1] = fmaf(a4.x, b4.y, acc[ 1]);
            acc[ 2] = fmaf(a4.x, b4.z, acc[ 2]);
            acc[ 3] = fmaf(a4.x, b4.w, acc[ 3]);
            acc[ 4] = fmaf(a4.y, b4.x, acc[ 4]);
            acc[ 5] = fmaf(a4.y, b4.y, acc[ 5]);
            acc[ 6] = fmaf(a4.y, b4.z, acc[ 6]);
            acc[ 7] = fmaf(a4.y, b4.w, acc[ 7]);
            acc[ 8] = fmaf(a4.z, b4.x, acc[ 8]);
            acc[ 9] = fmaf(a4.z, b4.y, acc[ 9]);
            acc[10] = fmaf(a4.z, b4.z, acc[10]);
            acc[11] = fmaf(a4.z, b4.w, acc[11]);
            acc[12] = fmaf(a4.w, b4.x, acc[12]);
            acc[13] = fmaf(a4.w, b4.y, acc[13]);
            acc[14] = fmaf(a4.w, b4.z, acc[14]);
            acc[15] = fmaf(a4.w, b4.w, acc[15]);
        }
        __syncthreads();
        c = cn;
    }

    #pragma unroll
    for (int j = 0; j < 4; j++) {
        int m = m0 + ty + j;
        #pragma unroll
        for (int cc = 0; cc < 4; cc++) {
            int o = tx + cc;
            if (o < co) atomicAdd(outbuf + (size_t)m*ow + o, acc[j*4 + cc]);
        }
    }
}

// ---------------- host ----------------
extern "C" void kernel_launch(void* const* d_in, const int* in_sizes, int n_in,
                              void* d_out, int out_size)
{
    const float* p     = (const float*)d_in[0];
    const float* v     = (const float*)d_in[1];
    const float* other = (const float*)d_in[2];
    const float* mask  = (const float*)d_in[3];
    const float* kf    = (const float*)d_in[4];
    const float* Wf    = (const float*)d_in[5];
    const float* bf    = (const float*)d_in[6];
    const float* k1    = (const float*)d_in[7];
    const float* W1    = (const float*)d_in[8];
    const float* b1    = (const float*)d_in[9];
    const float* k2    = (const float*)d_in[10];
    const float* W2    = (const float*)d_in[11];
    const float* b2    = (const float*)d_in[12];
    const float* k3    = (const float*)d_in[13];
    const float* W3    = (const float*)d_in[14];
    const float* b3    = (const float*)d_in[15];
    const float* k4    = (const float*)d_in[16];
    const float* W4    = (const float*)d_in[17];
    const float* b4    = (const float*)d_in[18];
    float* out = (float*)d_out;

    // launch order matters: ncu captures launch index 5 (convA layer 1)
    prep_feats_kernel<<<64, 256>>>(v, other);                       // 0
    prep_k2_kernel<<<dim3(32,5), 256>>>(kf, k1, k2, k3, k4);        // 1
    geom_kernel<<<NP, 256>>>(p, mask);                              // 2

    convA_kernel<<<NP, 256>>>(0, 0, 66, 68, Wf, bf, 0, out, 0);     // 3
    convB_kernel<<<dim3(8, CB_NKS), 256>>>(0, 4224, 32, 64, 0, out);// 4

    convA_kernel<<<NP, 256>>>(1, 1, 64, 64, W1, b1, 1, out, 1);     // 5 <- ncu capture
    convB_kernel<<<dim3(8, CB_NKS), 256>>>(1, 4096, 64, 64, 1, out);

    convA_kernel<<<NP, 256>>>(2, 1, 64, 64, W2, b2, 0, out, 1);
    convB_kernel<<<dim3(8, CB_NKS), 256>>>(2, 4096, 64, 64, 0, out);

    convA_kernel<<<NP, 256>>>(1, 1, 64, 64, W3, b3, 1, out, 1);
    convB_kernel<<<dim3(8, CB_NKS), 256>>>(3, 4096, 64, 64, 1, out);

    convA_kernel<<<NP, 256>>>(2, 1, 64, 64, W4, b4, 2, out, 2);
    convB_kernel<<<dim3(8, CB_NKS), 256>>>(4, 4096, 6, 6, 2, out);
}

// round 7
// speedup vs baseline: 1.3338x; 1.3338x over previous
#include <cuda_runtime.h>
#include <math.h>

#define NP 512
#define GD 64
#define K2STRIDE (4224*64)
#define CB_BK 32
#define CB_NKS 64
#define ENT_PER_M 4096   // worst case: 512 pairs * 8 taps

// ---------------- scratch (device globals; no allocations) ----------------
__device__ float d_h0[NP*68];                 // layer-0 features, stride 68
__device__ float d_bufA[NP*64];               // ping-pong layer outputs
__device__ float d_bufB[NP*64];
__device__ float d_t[NP*GD*66];               // t[m][g*ci + i]
__device__ int   d_goff[NP*GD];               // CSR: absolute offset of (m,g) entry list
__device__ int   d_gcnt[NP*GD];               // CSR: entry count per (m,g)
__device__ uint2 d_gent[NP*ENT_PER_M];        // CSR entries: {n, weight}
__device__ float d_K2[5*K2STRIDE];            // K rearranged: [(g*ci+i)][o] per layer

// ---------------- prep 1: layer-0 features ----------------
__global__ void prep_feats_kernel(const float* __restrict__ v, const float* __restrict__ other)
{
    int stride = gridDim.x * blockDim.x;
    for (int e = blockIdx.x * blockDim.x + threadIdx.x; e < NP*68; e += stride) {
        int n = e / 68, i = e - n*68;
        float val;
        if (i == 0)       val = 1.0f;
        else if (i < 4)   val = v[n*3 + (i-1)];
        else if (i < 66)  val = other[n*62 + (i-4)];
        else              val = 0.0f;
        d_h0[e] = val;
    }
}

// ---------------- prep 2: rearranged conv kernels ----------------
__global__ void prep_k2_kernel(const float* __restrict__ k0, const float* __restrict__ k1,
                               const float* __restrict__ k2, const float* __restrict__ k3,
                               const float* __restrict__ k4)
{
    int l = blockIdx.y;
    const float* src = (l==0)?k0 : (l==1)?k1 : (l==2)?k2 : (l==3)?k3 : k4;
    int ci = (l==0) ? 66 : 64;
    int co = (l==0) ? 32 : ((l==4) ? 6 : 64);
    int tot = GD*ci*co;
    float* dst = d_K2 + l*K2STRIDE;
    int stride = gridDim.x * blockDim.x;
    for (int e = blockIdx.x * blockDim.x + threadIdx.x; e < tot; e += stride) {
        int o  = e % co;
        int t2 = e / co;
        int i  = t2 % ci;
        int g  = t2 / ci;
        dst[e] = src[(o*ci + i)*GD + g];
    }
}

// ---------------- geometry + CSR build (layer-invariant, built once) ----------------
__global__ void __launch_bounds__(256) geom_kernel(const float* __restrict__ p,
                                                   const float* __restrict__ mask)
{
    __shared__ float s_w8[NP][8];
    __shared__ unsigned long long s_gp[NP];
    __shared__ unsigned short s_n[NP];
    __shared__ int s_cnt[8];
    __shared__ int s_gc[64];
    __shared__ int s_go[64];

    int m = blockIdx.x;
    int tid = threadIdx.x;
    int lane = tid & 31, warp = tid >> 5;
    float pmx = p[m*3+0], pmy = p[m*3+1], pmz = p[m*3+2];
    const float INV_R = 1.0f/40.0f;
    const float C4PI  = 1.2732395447351628f;
    int cnt = 0;
    int cbase = warp*64;
    #pragma unroll
    for (int round = 0; round < 2; round++) {
        int n = cbase + round*32 + lane;
        float rx = (p[n*3+0]-pmx)*INV_R;
        float ry = (p[n*3+1]-pmy)*INV_R;
        float rz = (p[n*3+2]-pmz)*INV_R;
        float r2 = rx*rx + ry*ry + rz*rz;
        float mk = mask[n];
        float t1 = 1.0f - r2;
        bool active = (t1 > 0.0f) && (mk != 0.0f);
        float w8[8];
        unsigned long long gp = 0ull;
        if (active) {
            float att = t1*t1*t1*mk;
            float r = sqrtf(rx*rx + ry*ry + 1e-9f);
            float xs, ys;
            if (rx == 0.0f && ry == 0.0f) { xs = 0.0f; ys = 0.0f; }
            else if (fabsf(ry) <= fabsf(rx)) {
                float s = copysignf(r, rx);
                xs = s;
                ys = C4PI * s * atanf(ry / rx);
            } else {
                float s = copysignf(r, ry);
                ys = s;
                xs = C4PI * s * atanf(rx / ry);
            }
            float zs = rz;
            float cz = 2.0f*zs + 1.5f, cy = 2.0f*ys + 1.5f, cx = 2.0f*xs + 1.5f;
            float fz0 = floorf(cz), fy0 = floorf(cy), fx0 = floorf(cx);
            int iz = (int)fz0, iy = (int)fy0, ix = (int)fx0;
            float fz = cz - fz0, fy = cy - fy0, fx = cx - fx0;
            float wz[2] = {1.0f-fz, fz};
            float wy[2] = {1.0f-fy, fy};
            float wx[2] = {1.0f-fx, fx};
            #pragma unroll
            for (int dz = 0; dz < 2; dz++)
            #pragma unroll
            for (int dy = 0; dy < 2; dy++)
            #pragma unroll
            for (int dx = 0; dx < 2; dx++) {
                int k = dz*4 + dy*2 + dx;
                int z = iz+dz, y = iy+dy, x = ix+dx;
                bool valid = ((unsigned)z < 4u) && ((unsigned)y < 4u) && ((unsigned)x < 4u);
                float w = valid ? (wz[dz]*wy[dy]*wx[dx]*att) : 0.0f;
                int g = valid ? (z*16 + y*4 + x) : 64;
                w8[k] = w;
                gp |= ((unsigned long long)(unsigned)g) << (8*k);
            }
        }
        unsigned bal = __ballot_sync(0xffffffffu, active);
        int pos = cnt + __popc(bal & ((1u << lane) - 1u));
        if (active) {
            int slot = cbase + pos;
            s_n[slot]  = (unsigned short)n;
            s_gp[slot] = gp;
            #pragma unroll
            for (int k = 0; k < 8; k++) s_w8[slot][k] = w8[k];
        }
        cnt += __popc(bal);
    }
    if (lane == 0) s_cnt[warp] = cnt;
    __syncthreads();

    if (tid < 64) {
        int g = tid;
        int count = 0;
        for (int c = 0; c < 8; c++) {
            int cn = s_cnt[c];
            for (int j = 0; j < cn; j++) {
                unsigned long long gp = s_gp[c*64 + j];
                #pragma unroll
                for (int k = 0; k < 8; k++)
                    if ((int)((gp >> (8*k)) & 255ull) == g) count++;
            }
        }
        s_gc[g] = count;
    }
    __syncthreads();
    if (tid == 0) {
        int acc = 0;
        for (int g = 0; g < 64; g++) { s_go[g] = acc; acc += s_gc[g]; }
    }
    __syncthreads();
    if (tid < 64) {
        int g = tid;
        int pos = m*ENT_PER_M + s_go[g];
        d_goff[m*64 + g] = pos;
        d_gcnt[m*64 + g] = s_gc[g];
        for (int c = 0; c < 8; c++) {
            int cn = s_cnt[c];
            for (int j = 0; j < cn; j++) {
                int slot = c*64 + j;
                unsigned long long gp = s_gp[slot];
                #pragma unroll
                for (int k = 0; k < 8; k++) {
                    if ((int)((gp >> (8*k)) & 255ull) == g) {
                        uint2 e;
                        e.x = (unsigned)s_n[slot];
                        e.y = __float_as_uint(s_w8[slot][k]);
                        d_gent[pos] = e;
                        pos++;
                    }
                }
            }
        }
    }
}

// ---------------- kernel A: CSR gather into registers + dense tail ----------------
// grid (NP, 4); 256 thr = 8 warps. Warp owns exactly 2 interleaved g-lists:
// g0 = warp*4 + blockIdx.y (0..31), g1 = g0 + 32. Fine-grained balance + MLP=2 lists.
__global__ void __launch_bounds__(256) convA_kernel(
    int finsel, int dorelu, int ci, int fstride,
    const float* __restrict__ W, const float* __restrict__ bias,
    int outsel, float* __restrict__ dout, int mode)
{
    const float* fin = (finsel==0) ? d_h0 : (finsel==1) ? d_bufA : d_bufB;
    float* outbuf = (outsel==0) ? d_bufA : (outsel==1) ? d_bufB : dout;

    int m = blockIdx.x;
    int gq = blockIdx.y;
    int tid = threadIdx.x;
    int lane = tid & 31, warp = tid >> 5;
    bool extra = (ci == 66) && (lane < 2);

    int g0 = warp*4 + gq;
    int g1 = g0 + 32;
    int off0 = d_goff[m*64 + g0], c0 = d_gcnt[m*64 + g0];
    int off1 = d_goff[m*64 + g1], c1 = d_gcnt[m*64 + g1];
    const uint2* e0p = d_gent + off0;
    const uint2* e1p = d_gent + off1;
    float ax0 = 0.f, ay0 = 0.f, ae0 = 0.f;
    float ax1 = 0.f, ay1 = 0.f, ae1 = 0.f;
    int cmax = max(c0, c1);
    #pragma unroll 2
    for (int e = 0; e < cmax; e++) {
        uint2 ea = (e < c0) ? __ldg(e0p + e) : make_uint2(0u, 0u);
        uint2 eb = (e < c1) ? __ldg(e1p + e) : make_uint2(0u, 0u);
        float w0 = __uint_as_float(ea.y);
        float w1 = __uint_as_float(eb.y);
        const float* fr0 = fin + ea.x * fstride;
        const float* fr1 = fin + eb.x * fstride;
        float2 fA = *(const float2*)(fr0 + 2*lane);
        float2 fB = *(const float2*)(fr1 + 2*lane);
        if (dorelu) {
            fA.x = fmaxf(fA.x, 0.0f); fA.y = fmaxf(fA.y, 0.0f);
            fB.x = fmaxf(fB.x, 0.0f); fB.y = fmaxf(fB.y, 0.0f);
        }
        ax0 = fmaf(w0, fA.x, ax0); ay0 = fmaf(w0, fA.y, ay0);
        ax1 = fmaf(w1, fB.x, ax1); ay1 = fmaf(w1, fB.y, ay1);
        if (extra) {
            float fe0 = fr0[64 + lane];
            float fe1 = fr1[64 + lane];
            if (dorelu) { fe0 = fmaxf(fe0, 0.0f); fe1 = fmaxf(fe1, 0.0f); }
            ae0 = fmaf(w0, fe0, ae0);
            ae1 = fmaf(w1, fe1, ae1);
        }
    }
    float* tp0 = d_t + (size_t)m*(64*ci) + g0*ci;
    float* tp1 = d_t + (size_t)m*(64*ci) + g1*ci;
    tp0[2*lane] = ax0; tp0[2*lane + 1] = ay0;
    tp1[2*lane] = ax1; tp1[2*lane + 1] = ay1;
    if (extra) { tp0[64 + lane] = ae0; tp1[64 + lane] = ae1; }

    // dense tail (single block slice): initialize out buffer; convB atomic-adds conv part.
    if (gq == 0) {
        if (mode == 0) {
            if (tid < 64) {
                float val = 0.0f;
                if (tid >= 32) {
                    int o = tid - 32;
                    float acc = bias[o];
                    for (int i = 0; i < 66; i++) acc = fmaf(fin[m*68 + i], W[o*66 + i], acc);
                    val = acc;
                }
                outbuf[m*64 + tid] = val;
            }
        } else if (mode == 1) {
            if (tid < 64) {
                int o = tid;
                float acc = bias[o] + fin[m*64 + o];   // residual (raw, no relu)
                for (int i = 0; i < 64; i++)
                    acc = fmaf(fmaxf(fin[m*64 + i], 0.0f), W[o*64 + i], acc);
                outbuf[m*64 + o] = acc;
            }
        } else {
            if (tid < 6) {
                int o = tid;
                float acc = bias[o];
                for (int i = 0; i < 64; i++)
                    acc = fmaf(fmaxf(fin[m*64 + i], 0.0f), W[o*64 + i], acc);
                outbuf[m*6 + o] = acc;
            }
        }
    }
}

// ---------------- kernel B: k-split tiled GEMM  out[m][o] += sum_k t[m][k]*K2[k][o] --------
__global__ void __launch_bounds__(256) convB_kernel(
    int layer, int Ktot, int co, int ow, int outsel, float* __restrict__ dout)
{
    __shared__ float sA[CB_BK][68];   // [k][m]
    __shared__ float sB[CB_BK][64];   // [k][o]
    const float* K2l = d_K2 + layer*K2STRIDE;
    float* outbuf = (outsel==0) ? d_bufA : (outsel==1) ? d_bufB : dout;

    int m0 = blockIdx.x * 64;
    int tid = threadIdx.x;
    int nchunks = (Ktot + CB_BK - 1) / CB_BK;

    int mA = tid & 63;
    int kA = (tid >> 6) * 8;
    const float* tbase = d_t + (size_t)(m0 + mA) * Ktot;
    int kB = tid >> 3;
    int oB = (tid & 7) * 8;

    int tx = (tid & 15) * 4;
    int ty = (tid >> 4) * 4;

    float acc[16];
    #pragma unroll
    for (int j = 0; j < 16; j++) acc[j] = 0.0f;

    float ra[8], rb[8];

    int c = blockIdx.y;
    if (c >= nchunks) return;
    {
        int kb = c * CB_BK;
        int ka0 = kb + kA;
        if (ka0 + 7 < Ktot) {
            float4 v0 = *(const float4*)(tbase + ka0);
            float4 v1 = *(const float4*)(tbase + ka0 + 4);
            ra[0]=v0.x; ra[1]=v0.y; ra[2]=v0.z; ra[3]=v0.w;
            ra[4]=v1.x; ra[5]=v1.y; ra[6]=v1.z; ra[7]=v1.w;
        } else {
            #pragma unroll
            for (int j = 0; j < 8; j++) ra[j] = (ka0 + j < Ktot) ? tbase[ka0 + j] : 0.0f;
        }
        int kg = kb + kB;
        if (co == 64 && kg < Ktot) {
            const float* bp = K2l + (size_t)kg*64 + oB;
            float4 v0 = *(const float4*)bp;
            float4 v1 = *(const float4*)(bp + 4);
            rb[0]=v0.x; rb[1]=v0.y; rb[2]=v0.z; rb[3]=v0.w;
            rb[4]=v1.x; rb[5]=v1.y; rb[6]=v1.z; rb[7]=v1.w;
        } else {
            #pragma unroll
            for (int j = 0; j < 8; j++)
                rb[j] = (kg < Ktot && (oB + j) < co) ? K2l[(size_t)kg*co + oB + j] : 0.0f;
        }
    }

    while (c < nchunks) {
        #pragma unroll
        for (int j = 0; j < 8; j++) sA[kA + j][mA] = ra[j];
        #pragma unroll
        for (int j = 0; j < 8; j++) sB[kB][oB + j] = rb[j];
        __syncthreads();

        int cn = c + CB_NKS;
        if (cn < nchunks) {
            int kb = cn * CB_BK;
            int ka0 = kb + kA;
            if (ka0 + 7 < Ktot) {
                float4 v0 = *(const float4*)(tbase + ka0);
                float4 v1 = *(const float4*)(tbase + ka0 + 4);
                ra[0]=v0.x; ra[1]=v0.y; ra[2]=v0.z; ra[3]=v0.w;
                ra[4]=v1.x; ra[5]=v1.y; ra[6]=v1.z; ra[7]=v1.w;
            } else {
                #pragma unroll
                for (int j = 0; j < 8; j++) ra[j] = (ka0 + j < Ktot) ? tbase[ka0 + j] : 0.0f;
            }
            int kg = kb + kB;
            if (co == 64 && kg < Ktot) {
                const float* bp = K2l + (size_t)kg*64 + oB;
                float4 v0 = *(const float4*)bp;
                float4 v1 = *(const float4*)(bp + 4);
                rb[0]=v0.x; rb[1]=v0.y; rb[2]=v0.z; rb[3]=v0.w;
                rb[4]=v1.x; rb[5]=v1.y; rb[6]=v1.z; rb[7]=v1.w;
            } else {
                #pragma unroll
                for (int j = 0; j < 8; j++)
                    rb[j] = (kg < Ktot && (oB + j) < co) ? K2l[(size_t)kg*co + oB + j] : 0.0f;
            }
        }

        #pragma unroll
        for (int k = 0; k < CB_BK; k++) {
            float4 b4 = *(const float4*)&sB[k][tx];
            float4 a4 = *(const float4*)&sA[k][ty];
            acc[ 0] = fmaf(a4.x, b4.x, acc[ 0]);
            acc[ 1] = fmaf(a4.x, b4.y, acc[ 1]);
            acc[ 2] = fmaf(a4.x, b4.z, acc[ 2]);
            acc[ 3] = fmaf(a4.x, b4.w, acc[ 3]);
            acc[ 4] = fmaf(a4.y, b4.x, acc[ 4]);
            acc[ 5] = fmaf(a4.y, b4.y, acc[ 5]);
            acc[ 6] = fmaf(a4.y, b4.z, acc[ 6]);
            acc[ 7] = fmaf(a4.y, b4.w, acc[ 7]);
            acc[ 8] = fmaf(a4.z, b4.x, acc[ 8]);
            acc[ 9] = fmaf(a4.z, b4.y, acc[ 9]);
            acc[10] = fmaf(a4.z, b4.z, acc[10]);
            acc[11] = fmaf(a4.z, b4.w, acc[11]);
            acc[12] = fmaf(a4.w, b4.x, acc[12]);
            acc[13] = fmaf(a4.w, b4.y, acc[13]);
            acc[14] = fmaf(a4.w, b4.z, acc[14]);
            acc[15] = fmaf(a4.w, b4.w, acc[15]);
        }
        __syncthreads();
        c = cn;
    }

    #pragma unroll
    for (int j = 0; j < 4; j++) {
        int m = m0 + ty + j;
        #pragma unroll
        for (int cc = 0; cc < 4; cc++) {
            int o = tx + cc;
            if (o < co) atomicAdd(outbuf + (size_t)m*ow + o, acc[j*4 + cc]);
        }
    }
}

// ---------------- host ----------------
extern "C" void kernel_launch(void* const* d_in, const int* in_sizes, int n_in,
                              void* d_out, int out_size)
{
    const float* p     = (const float*)d_in[0];
    const float* v     = (const float*)d_in[1];
    const float* other = (const float*)d_in[2];
    const float* mask  = (const float*)d_in[3];
    const float* kf    = (const float*)d_in[4];
    const float* Wf    = (const float*)d_in[5];
    const float* bf    = (const float*)d_in[6];
    const float* k1    = (const float*)d_in[7];
    const float* W1    = (const float*)d_in[8];
    const float* b1    = (const float*)d_in[9];
    const float* k2    = (const float*)d_in[10];
    const float* W2    = (const float*)d_in[11];
    const float* b2    = (const float*)d_in[12];
    const float* k3    = (const float*)d_in[13];
    const float* W3    = (const float*)d_in[14];
    const float* b3    = (const float*)d_in[15];
    const float* k4    = (const float*)d_in[16];
    const float* W4    = (const float*)d_in[17];
    const float* b4    = (const float*)d_in[18];
    float* out = (float*)d_out;

    // launch order matters: ncu captures launch index 5 (convA layer 1)
    prep_feats_kernel<<<64, 256>>>(v, other);                       // 0
    prep_k2_kernel<<<dim3(32,5), 256>>>(kf, k1, k2, k3, k4);        // 1
    geom_kernel<<<NP, 256>>>(p, mask);                              // 2

    convA_kernel<<<dim3(NP,4), 256>>>(0, 0, 66, 68, Wf, bf, 0, out, 0);   // 3
    convB_kernel<<<dim3(8, CB_NKS), 256>>>(0, 4224, 32, 64, 0, out);      // 4

    convA_kernel<<<dim3(NP,4), 256>>>(1, 1, 64, 64, W1, b1, 1, out, 1);   // 5 <- ncu capture
    convB_kernel<<<dim3(8, CB_NKS), 256>>>(1, 4096, 64, 64, 1, out);

    convA_kernel<<<dim3(NP,4), 256>>>(2, 1, 64, 64, W2, b2, 0, out, 1);
    convB_kernel<<<dim3(8, CB_NKS), 256>>>(2, 4096, 64, 64, 0, out);

    convA_kernel<<<dim3(NP,4), 256>>>(1, 1, 64, 64, W3, b3, 1, out, 1);
    convB_kernel<<<dim3(8, CB_NKS), 256>>>(3, 4096, 64, 64, 1, out);

    convA_kernel<<<dim3(NP,4), 256>>>(2, 1, 64, 64, W4, b4, 2, out, 2);
    convB_kernel<<<dim3(8, CB_NKS), 256>>>(4, 4096, 6, 6, 2, out);
}

// round 8
// speedup vs baseline: 1.9388x; 1.4535x over previous
#include <cuda_runtime.h>
#include <math.h>

#define NP 512
#define GD 64
#define K2STRIDE (4224*64)
#define CB_BK 32
#define CB_NKS 64
#define ENT_PER_M 4096   // worst case: 512 pairs * 8 taps

// ---------------- scratch (device globals; no allocations) ----------------
__device__ float d_h0[NP*68];                 // layer-0 features, stride 68
__device__ float d_hr[NP*64];                 // pre-relu'd features for next layer
__device__ float d_bufA[NP*64];               // ping-pong layer outputs (raw)
__device__ float d_bufB[NP*64];
__device__ float d_t[NP*GD*66];               // t[m][g*ci + i]
__device__ int   d_goff[NP*GD];               // CSR: absolute offset of (m,g) entry list
__device__ int   d_gcnt[NP*GD];               // CSR: entry count per (m,g)
__device__ uint2 d_gent[NP*ENT_PER_M];        // CSR entries: {n, weight}
__device__ float d_K2[5*K2STRIDE];            // K rearranged: [(g*ci+i)][o] per layer

// ---------------- prep: feats0 + rearranged kernels (one launch, tasks on gridDim.y) ----
__global__ void prep_kernel(const float* __restrict__ v, const float* __restrict__ other,
                            const float* __restrict__ k0, const float* __restrict__ k1,
                            const float* __restrict__ k2, const float* __restrict__ k3,
                            const float* __restrict__ k4)
{
    int task = blockIdx.y;
    int stride = gridDim.x * blockDim.x;
    int start = blockIdx.x * blockDim.x + threadIdx.x;
    if (task == 0) {
        for (int e = start; e < NP*68; e += stride) {
            int n = e / 68, i = e - n*68;
            float val;
            if (i == 0)       val = 1.0f;
            else if (i < 4)   val = v[n*3 + (i-1)];
            else if (i < 66)  val = other[n*62 + (i-4)];
            else              val = 0.0f;
            d_h0[e] = val;
        }
    } else {
        int l = task - 1;
        const float* src = (l==0)?k0 : (l==1)?k1 : (l==2)?k2 : (l==3)?k3 : k4;
        int ci = (l==0) ? 66 : 64;
        int co = (l==0) ? 32 : ((l==4) ? 6 : 64);
        int tot = GD*ci*co;
        float* dst = d_K2 + l*K2STRIDE;
        for (int e = start; e < tot; e += stride) {
            int o  = e % co;
            int t2 = e / co;
            int i  = t2 % ci;
            int g  = t2 / ci;
            dst[e] = src[(o*ci + i)*GD + g];
        }
    }
}

// ---------------- geometry + CSR build (layer-invariant, built once) ----------------
__global__ void __launch_bounds__(256) geom_kernel(const float* __restrict__ p,
                                                   const float* __restrict__ mask)
{
    __shared__ float s_w8[NP][8];
    __shared__ unsigned long long s_gp[NP];
    __shared__ unsigned short s_n[NP];
    __shared__ int s_cnt[8];
    __shared__ int s_gc[64];
    __shared__ int s_go[64];

    int m = blockIdx.x;
    int tid = threadIdx.x;
    int lane = tid & 31, warp = tid >> 5;
    float pmx = p[m*3+0], pmy = p[m*3+1], pmz = p[m*3+2];
    const float INV_R = 1.0f/40.0f;
    const float C4PI  = 1.2732395447351628f;
    int cnt = 0;
    int cbase = warp*64;
    #pragma unroll
    for (int round = 0; round < 2; round++) {
        int n = cbase + round*32 + lane;
        float rx = (p[n*3+0]-pmx)*INV_R;
        float ry = (p[n*3+1]-pmy)*INV_R;
        float rz = (p[n*3+2]-pmz)*INV_R;
        float r2 = rx*rx + ry*ry + rz*rz;
        float mk = mask[n];
        float t1 = 1.0f - r2;
        bool active = (t1 > 0.0f) && (mk != 0.0f);
        float w8[8];
        unsigned long long gp = 0ull;
        if (active) {
            float att = t1*t1*t1*mk;
            float r = sqrtf(rx*rx + ry*ry + 1e-9f);
            float xs, ys;
            if (rx == 0.0f && ry == 0.0f) { xs = 0.0f; ys = 0.0f; }
            else if (fabsf(ry) <= fabsf(rx)) {
                float s = copysignf(r, rx);
                xs = s;
                ys = C4PI * s * atanf(ry / rx);
            } else {
                float s = copysignf(r, ry);
                ys = s;
                xs = C4PI * s * atanf(rx / ry);
            }
            float zs = rz;
            float cz = 2.0f*zs + 1.5f, cy = 2.0f*ys + 1.5f, cx = 2.0f*xs + 1.5f;
            float fz0 = floorf(cz), fy0 = floorf(cy), fx0 = floorf(cx);
            int iz = (int)fz0, iy = (int)fy0, ix = (int)fx0;
            float fz = cz - fz0, fy = cy - fy0, fx = cx - fx0;
            float wz[2] = {1.0f-fz, fz};
            float wy[2] = {1.0f-fy, fy};
            float wx[2] = {1.0f-fx, fx};
            #pragma unroll
            for (int dz = 0; dz < 2; dz++)
            #pragma unroll
            for (int dy = 0; dy < 2; dy++)
            #pragma unroll
            for (int dx = 0; dx < 2; dx++) {
                int k = dz*4 + dy*2 + dx;
                int z = iz+dz, y = iy+dy, x = ix+dx;
                bool valid = ((unsigned)z < 4u) && ((unsigned)y < 4u) && ((unsigned)x < 4u);
                float w = valid ? (wz[dz]*wy[dy]*wx[dx]*att) : 0.0f;
                int g = valid ? (z*16 + y*4 + x) : 64;
                w8[k] = w;
                gp |= ((unsigned long long)(unsigned)g) << (8*k);
            }
        }
        unsigned bal = __ballot_sync(0xffffffffu, active);
        int pos = cnt + __popc(bal & ((1u << lane) - 1u));
        if (active) {
            int slot = cbase + pos;
            s_n[slot]  = (unsigned short)n;
            s_gp[slot] = gp;
            #pragma unroll
            for (int k = 0; k < 8; k++) s_w8[slot][k] = w8[k];
        }
        cnt += __popc(bal);
    }
    if (lane == 0) s_cnt[warp] = cnt;
    __syncthreads();

    if (tid < 64) {
        int g = tid;
        int count = 0;
        for (int c = 0; c < 8; c++) {
            int cn = s_cnt[c];
            for (int j = 0; j < cn; j++) {
                unsigned long long gp = s_gp[c*64 + j];
                #pragma unroll
                for (int k = 0; k < 8; k++)
                    if ((int)((gp >> (8*k)) & 255ull) == g) count++;
            }
        }
        s_gc[g] = count;
    }
    __syncthreads();
    if (tid == 0) {
        int acc = 0;
        for (int g = 0; g < 64; g++) { s_go[g] = acc; acc += s_gc[g]; }
    }
    __syncthreads();
    if (tid < 64) {
        int g = tid;
        int pos = m*ENT_PER_M + s_go[g];
        d_goff[m*64 + g] = pos;
        d_gcnt[m*64 + g] = s_gc[g];
        for (int c = 0; c < 8; c++) {
            int cn = s_cnt[c];
            for (int j = 0; j < cn; j++) {
                int slot = c*64 + j;
                unsigned long long gp = s_gp[slot];
                #pragma unroll
                for (int k = 0; k < 8; k++) {
                    if ((int)((gp >> (8*k)) & 255ull) == g) {
                        uint2 e;
                        e.x = (unsigned)s_n[slot];
                        e.y = __float_as_uint(s_w8[slot][k]);
                        d_gent[pos] = e;
                        pos++;
                    }
                }
            }
        }
    }
}

// ---------------- relu: produce pre-relu'd feature buffer for next layer ----------------
__global__ void relu_kernel(int insel)
{
    const float* src = (insel == 0) ? d_bufA : d_bufB;
    int i = blockIdx.x * 256 + threadIdx.x;
    d_hr[i] = fmaxf(src[i], 0.0f);
}

// ---------------- kernel A: CSR gather (no relu, compile-time strides) + dense tail ----
// grid (NP, 4); 256 thr = 8 warps. Warp owns 2 interleaved g-lists:
// g0 = warp*4 + blockIdx.y, g1 = g0 + 32.
template<int CI, int FSTRIDE, int FINSEL>
__global__ void __launch_bounds__(256) convA_t(
    const float* __restrict__ W, const float* __restrict__ bias,
    int outsel, float* __restrict__ dout, int mode, int residsel)
{
    const float* fin = (FINSEL == 0) ? d_h0 : d_hr;
    float* outbuf = (outsel==0) ? d_bufA : (outsel==1) ? d_bufB : dout;

    int m = blockIdx.x;
    int gq = blockIdx.y;
    int tid = threadIdx.x;
    int lane = tid & 31, warp = tid >> 5;
    const bool extra = (CI == 66) && (lane < 2);

    int g0 = warp*4 + gq;
    int g1 = g0 + 32;
    int off0 = d_goff[m*64 + g0], c0 = d_gcnt[m*64 + g0];
    int off1 = d_goff[m*64 + g1], c1 = d_gcnt[m*64 + g1];
    const uint2* e0p = d_gent + off0;
    const uint2* e1p = d_gent + off1;
    float ax0 = 0.f, ay0 = 0.f, ae0 = 0.f;
    float ax1 = 0.f, ay1 = 0.f, ae1 = 0.f;
    int cmin = min(c0, c1);

    #pragma unroll 2
    for (int e = 0; e < cmin; e++) {
        uint2 ea = __ldg(e0p + e);
        uint2 eb = __ldg(e1p + e);
        float w0 = __uint_as_float(ea.y);
        float w1 = __uint_as_float(eb.y);
        const float* fr0 = fin + ea.x * FSTRIDE;
        const float* fr1 = fin + eb.x * FSTRIDE;
        float2 fA = *(const float2*)(fr0 + 2*lane);
        float2 fB = *(const float2*)(fr1 + 2*lane);
        ax0 = fmaf(w0, fA.x, ax0); ay0 = fmaf(w0, fA.y, ay0);
        ax1 = fmaf(w1, fB.x, ax1); ay1 = fmaf(w1, fB.y, ay1);
        if (extra) {
            ae0 = fmaf(w0, fr0[64 + lane], ae0);
            ae1 = fmaf(w1, fr1[64 + lane], ae1);
        }
    }
    // tails (at most one runs)
    #pragma unroll 2
    for (int e = cmin; e < c0; e++) {
        uint2 ea = __ldg(e0p + e);
        float w0 = __uint_as_float(ea.y);
        const float* fr0 = fin + ea.x * FSTRIDE;
        float2 fA = *(const float2*)(fr0 + 2*lane);
        ax0 = fmaf(w0, fA.x, ax0); ay0 = fmaf(w0, fA.y, ay0);
        if (extra) ae0 = fmaf(w0, fr0[64 + lane], ae0);
    }
    #pragma unroll 2
    for (int e = cmin; e < c1; e++) {
        uint2 eb = __ldg(e1p + e);
        float w1 = __uint_as_float(eb.y);
        const float* fr1 = fin + eb.x * FSTRIDE;
        float2 fB = *(const float2*)(fr1 + 2*lane);
        ax1 = fmaf(w1, fB.x, ax1); ay1 = fmaf(w1, fB.y, ay1);
        if (extra) ae1 = fmaf(w1, fr1[64 + lane], ae1);
    }

    float* tp0 = d_t + (size_t)m*(64*CI) + g0*CI;
    float* tp1 = d_t + (size_t)m*(64*CI) + g1*CI;
    tp0[2*lane] = ax0; tp0[2*lane + 1] = ay0;
    tp1[2*lane] = ax1; tp1[2*lane + 1] = ay1;
    if (extra) { tp0[64 + lane] = ae0; tp1[64 + lane] = ae1; }

    // dense tail (one block slice): initialize out buffer; convB atomic-adds conv part.
    if (gq == 0) {
        if (mode == 0) {
            if (tid < 64) {
                float val = 0.0f;
                if (tid >= 32) {
                    int o = tid - 32;
                    float acc = bias[o];
                    for (int i = 0; i < 66; i++) acc = fmaf(d_h0[m*68 + i], W[o*66 + i], acc);
                    val = acc;
                }
                outbuf[m*64 + tid] = val;
            }
        } else if (mode == 1) {
            if (tid < 64) {
                int o = tid;
                const float* resid = (residsel == 0) ? d_bufA : d_bufB;
                float acc = bias[o] + resid[m*64 + o];   // residual (raw)
                for (int i = 0; i < 64; i++)
                    acc = fmaf(d_hr[m*64 + i], W[o*64 + i], acc);
                outbuf[m*64 + o] = acc;
            }
        } else {
            if (tid < 6) {
                int o = tid;
                float acc = bias[o];
                for (int i = 0; i < 64; i++)
                    acc = fmaf(d_hr[m*64 + i], W[o*64 + i], acc);
                outbuf[m*6 + o] = acc;
            }
        }
    }
}

// ---------------- kernel B: k-split tiled GEMM  out[m][o] += sum_k t[m][k]*K2[k][o] --------
__global__ void __launch_bounds__(256) convB_kernel(
    int layer, int Ktot, int co, int ow, int outsel, float* __restrict__ dout)
{
    __shared__ float sA[CB_BK][68];   // [k][m]
    __shared__ float sB[CB_BK][64];   // [k][o]
    const float* K2l = d_K2 + layer*K2STRIDE;
    float* outbuf = (outsel==0) ? d_bufA : (outsel==1) ? d_bufB : dout;

    int m0 = blockIdx.x * 64;
    int tid = threadIdx.x;
    int nchunks = (Ktot + CB_BK - 1) / CB_BK;

    int mA = tid & 63;
    int kA = (tid >> 6) * 8;
    const float* tbase = d_t + (size_t)(m0 + mA) * Ktot;
    int kB = tid >> 3;
    int oB = (tid & 7) * 8;

    int tx = (tid & 15) * 4;
    int ty = (tid >> 4) * 4;

    float acc[16];
    #pragma unroll
    for (int j = 0; j < 16; j++) acc[j] = 0.0f;

    float ra[8], rb[8];

    int c = blockIdx.y;
    if (c >= nchunks) return;
    {
        int kb = c * CB_BK;
        int ka0 = kb + kA;
        if (ka0 + 7 < Ktot) {
            float4 v0 = *(const float4*)(tbase + ka0);
            float4 v1 = *(const float4*)(tbase + ka0 + 4);
            ra[0]=v0.x; ra[1]=v0.y; ra[2]=v0.z; ra[3]=v0.w;
            ra[4]=v1.x; ra[5]=v1.y; ra[6]=v1.z; ra[7]=v1.w;
        } else {
            #pragma unroll
            for (int j = 0; j < 8; j++) ra[j] = (ka0 + j < Ktot) ? tbase[ka0 + j] : 0.0f;
        }
        int kg = kb + kB;
        if (co == 64 && kg < Ktot) {
            const float* bp = K2l + (size_t)kg*64 + oB;
            float4 v0 = *(const float4*)bp;
            float4 v1 = *(const float4*)(bp + 4);
            rb[0]=v0.x; rb[1]=v0.y; rb[2]=v0.z; rb[3]=v0.w;
            rb[4]=v1.x; rb[5]=v1.y; rb[6]=v1.z; rb[7]=v1.w;
        } else {
            #pragma unroll
            for (int j = 0; j < 8; j++)
                rb[j] = (kg < Ktot && (oB + j) < co) ? K2l[(size_t)kg*co + oB + j] : 0.0f;
        }
    }

    while (c < nchunks) {
        #pragma unroll
        for (int j = 0; j < 8; j++) sA[kA + j][mA] = ra[j];
        #pragma unroll
        for (int j = 0; j < 8; j++) sB[kB][oB + j] = rb[j];
        __syncthreads();

        int cn = c + CB_NKS;
        if (cn < nchunks) {
            int kb = cn * CB_BK;
            int ka0 = kb + kA;
            if (ka0 + 7 < Ktot) {
                float4 v0 = *(const float4*)(tbase + ka0);
                float4 v1 = *(const float4*)(tbase + ka0 + 4);
                ra[0]=v0.x; ra[1]=v0.y; ra[2]=v0.z; ra[3]=v0.w;
                ra[4]=v1.x; ra[5]=v1.y; ra[6]=v1.z; ra[7]=v1.w;
            } else {
                #pragma unroll
                for (int j = 0; j < 8; j++) ra[j] = (ka0 + j < Ktot) ? tbase[ka0 + j] : 0.0f;
            }
            int kg = kb + kB;
            if (co == 64 && kg < Ktot) {
                const float* bp = K2l + (size_t)kg*64 + oB;
                float4 v0 = *(const float4*)bp;
                float4 v1 = *(const float4*)(bp + 4);
                rb[0]=v0.x; rb[1]=v0.y; rb[2]=v0.z; rb[3]=v0.w;
                rb[4]=v1.x; rb[5]=v1.y; rb[6]=v1.z; rb[7]=v1.w;
            } else {
                #pragma unroll
                for (int j = 0; j < 8; j++)
                    rb[j] = (kg < Ktot && (oB + j) < co) ? K2l[(size_t)kg*co + oB + j] : 0.0f;
            }
        }

        #pragma unroll
        for (int k = 0; k < CB_BK; k++) {
            float4 b4 = *(const float4*)&sB[k][tx];
            float4 a4 = *(const float4*)&sA[k][ty];
            acc[ 0] = fmaf(a4.x, b4.x, acc[ 0]);
            acc[ 1] = fmaf(a4.x, b4.y, acc[ 1]);
            acc[ 2] = fmaf(a4.x, b4.z, acc[ 2]);
            acc[ 3] = fmaf(a4.x, b4.w, acc[ 3]);
            acc[ 4] = fmaf(a4.y, b4.x, acc[ 4]);
            acc[ 5] = fmaf(a4.y, b4.y, acc[ 5]);
            acc[ 6] = fmaf(a4.y, b4.z, acc[ 6]);
            acc[ 7] = fmaf(a4.y, b4.w, acc[ 7]);
            acc[ 8] = fmaf(a4.z, b4.x, acc[ 8]);
            acc[ 9] = fmaf(a4.z, b4.y, acc[ 9]);
            acc[10] = fmaf(a4.z, b4.z, acc[10]);
            acc[11] = fmaf(a4.z, b4.w, acc[11]);
            acc[12] = fmaf(a4.w, b4.x, acc[12]);
            acc[13] = fmaf(a4.w, b4.y, acc[13]);
            acc[14] = fmaf(a4.w, b4.z, acc[14]);
            acc[15] = fmaf(a4.w, b4.w, acc[15]);
        }
        __syncthreads();
        c = cn;
    }

    #pragma unroll
    for (int j = 0; j < 4; j++) {
        int m = m0 + ty + j;
        #pragma unroll
        for (int cc = 0; cc < 4; cc++) {
            int o = tx + cc;
            if (o < co) atomicAdd(outbuf + (size_t)m*ow + o, acc[j*4 + cc]);
        }
    }
}

// ---------------- host ----------------
extern "C" void kernel_launch(void* const* d_in, const int* in_sizes, int n_in,
                              void* d_out, int out_size)
{
    const float* p     = (const float*)d_in[0];
    const float* v     = (const float*)d_in[1];
    const float* other = (const float*)d_in[2];
    const float* mask  = (const float*)d_in[3];
    const float* kf    = (const float*)d_in[4];
    const float* Wf    = (const float*)d_in[5];
    const float* bf    = (const float*)d_in[6];
    const float* k1    = (const float*)d_in[7];
    const float* W1    = (const float*)d_in[8];
    const float* b1    = (const float*)d_in[9];
    const float* k2    = (const float*)d_in[10];
    const float* W2    = (const float*)d_in[11];
    const float* b2    = (const float*)d_in[12];
    const float* k3    = (const float*)d_in[13];
    const float* W3    = (const float*)d_in[14];
    const float* b3    = (const float*)d_in[15];
    const float* k4    = (const float*)d_in[16];
    const float* W4    = (const float*)d_in[17];
    const float* b4    = (const float*)d_in[18];
    float* out = (float*)d_out;

    // ncu -s 5 captures launch index 5 = convA layer 1
    prep_kernel<<<dim3(64,6), 256>>>(v, other, kf, k1, k2, k3, k4);          // 0
    geom_kernel<<<NP, 256>>>(p, mask);                                        // 1

    // layer 0: feats0 -> bufA
    convA_t<66,68,0><<<dim3(NP,4), 256>>>(Wf, bf, 0, out, 0, -1);             // 2
    convB_kernel<<<dim3(8, CB_NKS), 256>>>(0, 4224, 32, 64, 0, out);          // 3
    relu_kernel<<<128, 256>>>(0);                                             // 4

    // layer 1: d_hr -> bufB (resid bufA)
    convA_t<64,64,1><<<dim3(NP,4), 256>>>(W1, b1, 1, out, 1, 0);              // 5 <- ncu
    convB_kernel<<<dim3(8, CB_NKS), 256>>>(1, 4096, 64, 64, 1, out);
    relu_kernel<<<128, 256>>>(1);

    // layer 2: d_hr -> bufA (resid bufB)
    convA_t<64,64,1><<<dim3(NP,4), 256>>>(W2, b2, 0, out, 1, 1);
    convB_kernel<<<dim3(8, CB_NKS), 256>>>(2, 4096, 64, 64, 0, out);
    relu_kernel<<<128, 256>>>(0);

    // layer 3: d_hr -> bufB (resid bufA)
    convA_t<64,64,1><<<dim3(NP,4), 256>>>(W3, b3, 1, out, 1, 0);
    convB_kernel<<<dim3(8, CB_NKS), 256>>>(3, 4096, 64, 64, 1, out);
    relu_kernel<<<128, 256>>>(1);

    // layer 4: d_hr -> d_out, co=6, no residual
    convA_t<64,64,1><<<dim3(NP,4), 256>>>(W4, b4, 2, out, 2, -1);
    convB_kernel<<<dim3(8, CB_NKS), 256>>>(4, 4096, 6, 6, 2, out);
}

// round 9
// speedup vs baseline: 2.6345x; 1.3589x over previous
#include <cuda_runtime.h>
#include <math.h>

#define NP 512
#define GD 64
#define K2STRIDE (4224*64)
#define CB_BK 32
#define CB_NKS 36
#define ENT_PER_M 4224   // worst case 4096 taps + 64 pad dummies, rounded

// ---------------- scratch (device globals; no allocations) ----------------
__device__ float d_h0[NP*68];                 // layer-0 features, stride 68
__device__ float d_hr[NP*64];                 // pre-relu'd features for next layer
__device__ float d_bufA[NP*64];               // ping-pong layer outputs (raw)
__device__ float d_bufB[NP*64];
__device__ float d_t[NP*GD*66];               // t[m][g*ci + i]
__device__ int   d_goff[NP*GD];               // CSR: absolute offset (even) of (m,g) list
__device__ int   d_gcnt[NP*GD];               // CSR: padded (even) entry count
__device__ uint2 d_gent[NP*ENT_PER_M];        // CSR entries: {n, weight}; dummies w=0
__device__ float d_K2[5*K2STRIDE];            // K rearranged: [(g*ci+i)][o] per layer

// ---------------- prep: feats0 + rearranged kernels ----------------
__global__ void prep_kernel(const float* __restrict__ v, const float* __restrict__ other,
                            const float* __restrict__ k0, const float* __restrict__ k1,
                            const float* __restrict__ k2, const float* __restrict__ k3,
                            const float* __restrict__ k4)
{
    int task = blockIdx.y;
    int stride = gridDim.x * blockDim.x;
    int start = blockIdx.x * blockDim.x + threadIdx.x;
    if (task == 0) {
        for (int e = start; e < NP*68; e += stride) {
            int n = e / 68, i = e - n*68;
            float val;
            if (i == 0)       val = 1.0f;
            else if (i < 4)   val = v[n*3 + (i-1)];
            else if (i < 66)  val = other[n*62 + (i-4)];
            else              val = 0.0f;
            d_h0[e] = val;
        }
    } else {
        int l = task - 1;
        const float* src = (l==0)?k0 : (l==1)?k1 : (l==2)?k2 : (l==3)?k3 : k4;
        int ci = (l==0) ? 66 : 64;
        int co = (l==0) ? 32 : ((l==4) ? 6 : 64);
        int tot = GD*ci*co;
        float* dst = d_K2 + l*K2STRIDE;
        for (int e = start; e < tot; e += stride) {
            int o  = e % co;
            int t2 = e / co;
            int i  = t2 % ci;
            int g  = t2 / ci;
            dst[e] = src[(o*ci + i)*GD + g];
        }
    }
}

// ---------------- geometry + CSR build (layer-invariant, built once) ----------------
__global__ void __launch_bounds__(256) geom_kernel(const float* __restrict__ p,
                                                   const float* __restrict__ mask)
{
    __shared__ float s_w8[NP][8];
    __shared__ unsigned long long s_gp[NP];
    __shared__ unsigned short s_n[NP];
    __shared__ int s_cnt[8];
    __shared__ int s_gc[64];     // true counts
    __shared__ int s_go[64];     // exclusive scan over padded counts
    __shared__ int s_pos[64];    // atomic fill cursors (absolute)

    int m = blockIdx.x;
    int tid = threadIdx.x;
    int lane = tid & 31, warp = tid >> 5;
    if (tid < 64) s_gc[tid] = 0;
    float pmx = p[m*3+0], pmy = p[m*3+1], pmz = p[m*3+2];
    const float INV_R = 1.0f/40.0f;
    const float C4PI  = 1.2732395447351628f;
    int cnt = 0;
    int cbase = warp*64;
    #pragma unroll
    for (int round = 0; round < 2; round++) {
        int n = cbase + round*32 + lane;
        float rx = (p[n*3+0]-pmx)*INV_R;
        float ry = (p[n*3+1]-pmy)*INV_R;
        float rz = (p[n*3+2]-pmz)*INV_R;
        float r2 = rx*rx + ry*ry + rz*rz;
        float mk = mask[n];
        float t1 = 1.0f - r2;
        bool active = (t1 > 0.0f) && (mk != 0.0f);
        float w8[8];
        unsigned long long gp = 0ull;
        if (active) {
            float att = t1*t1*t1*mk;
            float r = sqrtf(rx*rx + ry*ry + 1e-9f);
            float xs, ys;
            if (rx == 0.0f && ry == 0.0f) { xs = 0.0f; ys = 0.0f; }
            else if (fabsf(ry) <= fabsf(rx)) {
                float s = copysignf(r, rx);
                xs = s;
                ys = C4PI * s * atanf(ry / rx);
            } else {
                float s = copysignf(r, ry);
                ys = s;
                xs = C4PI * s * atanf(rx / ry);
            }
            float zs = rz;
            float cz = 2.0f*zs + 1.5f, cy = 2.0f*ys + 1.5f, cx = 2.0f*xs + 1.5f;
            float fz0 = floorf(cz), fy0 = floorf(cy), fx0 = floorf(cx);
            int iz = (int)fz0, iy = (int)fy0, ix = (int)fx0;
            float fz = cz - fz0, fy = cy - fy0, fx = cx - fx0;
            float wz[2] = {1.0f-fz, fz};
            float wy[2] = {1.0f-fy, fy};
            float wx[2] = {1.0f-fx, fx};
            #pragma unroll
            for (int dz = 0; dz < 2; dz++)
            #pragma unroll
            for (int dy = 0; dy < 2; dy++)
            #pragma unroll
            for (int dx = 0; dx < 2; dx++) {
                int k = dz*4 + dy*2 + dx;
                int z = iz+dz, y = iy+dy, x = ix+dx;
                bool valid = ((unsigned)z < 4u) && ((unsigned)y < 4u) && ((unsigned)x < 4u);
                float w = valid ? (wz[dz]*wy[dy]*wx[dx]*att) : 0.0f;
                int g = valid ? (z*16 + y*4 + x) : 64;
                w8[k] = w;
                gp |= ((unsigned long long)(unsigned)g) << (8*k);
            }
        }
        unsigned bal = __ballot_sync(0xffffffffu, active);
        int pos = cnt + __popc(bal & ((1u << lane) - 1u));
        if (active) {
            int slot = cbase + pos;
            s_n[slot]  = (unsigned short)n;
            s_gp[slot] = gp;
            #pragma unroll
            for (int k = 0; k < 8; k++) s_w8[slot][k] = w8[k];
        }
        cnt += __popc(bal);
    }
    if (lane == 0) s_cnt[warp] = cnt;
    __syncthreads();

    // ---- count taps per g (parallel, shared atomics) ----
    for (int idx = tid; idx < NP; idx += 256) {
        int c = idx >> 6, j = idx & 63;
        if (j < s_cnt[c]) {
            unsigned long long gp = s_gp[idx];
            #pragma unroll
            for (int k = 0; k < 8; k++) {
                int g = (int)((gp >> (8*k)) & 255ull);
                if (g < 64) atomicAdd(&s_gc[g], 1);
            }
        }
    }
    __syncthreads();
    if (tid == 0) {
        int acc = 0;
        for (int g = 0; g < 64; g++) { s_go[g] = acc; acc += (s_gc[g] + 1) & ~1; }
    }
    __syncthreads();
    if (tid < 64) {
        int g = tid;
        int base = m*ENT_PER_M + s_go[g];
        int tc = s_gc[g];
        d_goff[m*64 + g] = base;
        d_gcnt[m*64 + g] = (tc + 1) & ~1;    // padded count
        s_pos[g] = base;
        if (tc & 1) d_gent[base + tc] = make_uint2(0u, 0u);   // zero-weight dummy
    }
    __syncthreads();
    // ---- fill (parallel, atomic cursors; order arbitrary, sum tolerance-safe) ----
    for (int idx = tid; idx < NP; idx += 256) {
        int c = idx >> 6, j = idx & 63;
        if (j < s_cnt[c]) {
            unsigned long long gp = s_gp[idx];
            unsigned nn = (unsigned)s_n[idx];
            #pragma unroll
            for (int k = 0; k < 8; k++) {
                int g = (int)((gp >> (8*k)) & 255ull);
                if (g < 64) {
                    int pos = atomicAdd(&s_pos[g], 1);
                    d_gent[pos] = make_uint2(nn, __float_as_uint(s_w8[idx][k]));
                }
            }
        }
    }
}

// ---------------- relu: produce pre-relu'd feature buffer for next layer ----------------
__global__ void relu_kernel(int insel)
{
    const float* src = (insel == 0) ? d_bufA : d_bufB;
    int i = blockIdx.x * 256 + threadIdx.x;
    d_hr[i] = fmaxf(src[i], 0.0f);
}

// ---------------- kernel A: CSR gather, paired entries via LDG.128 + dense tail ----------
// grid (NP, 4); 256 thr = 8 warps. Warp owns 2 interleaved g-lists:
// g0 = warp*4 + blockIdx.y, g1 = g0 + 32. Lists are padded to even length.
template<int CI, int FSTRIDE, int FINSEL>
__global__ void __launch_bounds__(256) convA_t(
    const float* __restrict__ W, const float* __restrict__ bias,
    int outsel, float* __restrict__ dout, int mode, int residsel)
{
    const float* fin = (FINSEL == 0) ? d_h0 : d_hr;
    float* outbuf = (outsel==0) ? d_bufA : (outsel==1) ? d_bufB : dout;

    int m = blockIdx.x;
    int gq = blockIdx.y;
    int tid = threadIdx.x;
    int lane = tid & 31, warp = tid >> 5;
    const bool extra = (CI == 66) && (lane < 2);

    int g0 = warp*4 + gq;
    int g1 = g0 + 32;
    int off0 = d_goff[m*64 + g0], c0 = d_gcnt[m*64 + g0];
    int off1 = d_goff[m*64 + g1], c1 = d_gcnt[m*64 + g1];
    const uint4* e0p = (const uint4*)(d_gent + off0);   // 2 entries per uint4
    const uint4* e1p = (const uint4*)(d_gent + off1);
    int n0 = c0 >> 1, n1 = c1 >> 1;
    int nmin = min(n0, n1);

    float ax0 = 0.f, ay0 = 0.f, ae0 = 0.f;
    float ax1 = 0.f, ay1 = 0.f, ae1 = 0.f;

    #pragma unroll 2
    for (int e = 0; e < nmin; e++) {
        uint4 ea = __ldg(e0p + e);
        uint4 eb = __ldg(e1p + e);
        const float* fa0 = fin + ea.x * FSTRIDE;
        const float* fa1 = fin + ea.z * FSTRIDE;
        const float* fb0 = fin + eb.x * FSTRIDE;
        const float* fb1 = fin + eb.z * FSTRIDE;
        float wA0 = __uint_as_float(ea.y), wA1 = __uint_as_float(ea.w);
        float wB0 = __uint_as_float(eb.y), wB1 = __uint_as_float(eb.w);
        float2 A0 = *(const float2*)(fa0 + 2*lane);
        float2 A1 = *(const float2*)(fa1 + 2*lane);
        float2 B0 = *(const float2*)(fb0 + 2*lane);
        float2 B1 = *(const float2*)(fb1 + 2*lane);
        ax0 = fmaf(wA0, A0.x, ax0); ay0 = fmaf(wA0, A0.y, ay0);
        ax0 = fmaf(wA1, A1.x, ax0); ay0 = fmaf(wA1, A1.y, ay0);
        ax1 = fmaf(wB0, B0.x, ax1); ay1 = fmaf(wB0, B0.y, ay1);
        ax1 = fmaf(wB1, B1.x, ax1); ay1 = fmaf(wB1, B1.y, ay1);
        if (extra) {
            ae0 = fmaf(wA0, fa0[64 + lane], ae0);
            ae0 = fmaf(wA1, fa1[64 + lane], ae0);
            ae1 = fmaf(wB0, fb0[64 + lane], ae1);
            ae1 = fmaf(wB1, fb1[64 + lane], ae1);
        }
    }
    // tails (at most one runs)
    #pragma unroll 2
    for (int e = nmin; e < n0; e++) {
        uint4 ea = __ldg(e0p + e);
        const float* fa0 = fin + ea.x * FSTRIDE;
        const float* fa1 = fin + ea.z * FSTRIDE;
        float wA0 = __uint_as_float(ea.y), wA1 = __uint_as_float(ea.w);
        float2 A0 = *(const float2*)(fa0 + 2*lane);
        float2 A1 = *(const float2*)(fa1 + 2*lane);
        ax0 = fmaf(wA0, A0.x, ax0); ay0 = fmaf(wA0, A0.y, ay0);
        ax0 = fmaf(wA1, A1.x, ax0); ay0 = fmaf(wA1, A1.y, ay0);
        if (extra) {
            ae0 = fmaf(wA0, fa0[64 + lane], ae0);
            ae0 = fmaf(wA1, fa1[64 + lane], ae0);
        }
    }
    #pragma unroll 2
    for (int e = nmin; e < n1; e++) {
        uint4 eb = __ldg(e1p + e);
        const float* fb0 = fin + eb.x * FSTRIDE;
        const float* fb1 = fin + eb.z * FSTRIDE;
        float wB0 = __uint_as_float(eb.y), wB1 = __uint_as_float(eb.w);
        float2 B0 = *(const float2*)(fb0 + 2*lane);
        float2 B1 = *(const float2*)(fb1 + 2*lane);
        ax1 = fmaf(wB0, B0.x, ax1); ay1 = fmaf(wB0, B0.y, ay1);
        ax1 = fmaf(wB1, B1.x, ax1); ay1 = fmaf(wB1, B1.y, ay1);
        if (extra) {
            ae1 = fmaf(wB0, fb0[64 + lane], ae1);
            ae1 = fmaf(wB1, fb1[64 + lane], ae1);
        }
    }

    float* tp0 = d_t + (size_t)m*(64*CI) + g0*CI;
    float* tp1 = d_t + (size_t)m*(64*CI) + g1*CI;
    tp0[2*lane] = ax0; tp0[2*lane + 1] = ay0;
    tp1[2*lane] = ax1; tp1[2*lane + 1] = ay1;
    if (extra) { tp0[64 + lane] = ae0; tp1[64 + lane] = ae1; }

    // dense tail (one block slice): initialize out buffer; convB atomic-adds conv part.
    if (gq == 0) {
        if (mode == 0) {
            if (tid < 64) {
                float val = 0.0f;
                if (tid >= 32) {
                    int o = tid - 32;
                    float acc = bias[o];
                    for (int i = 0; i < 66; i++) acc = fmaf(d_h0[m*68 + i], W[o*66 + i], acc);
                    val = acc;
                }
                outbuf[m*64 + tid] = val;
            }
        } else if (mode == 1) {
            if (tid < 64) {
                int o = tid;
                const float* resid = (residsel == 0) ? d_bufA : d_bufB;
                float acc = bias[o] + resid[m*64 + o];   // residual (raw)
                for (int i = 0; i < 64; i++)
                    acc = fmaf(d_hr[m*64 + i], W[o*64 + i], acc);
                outbuf[m*64 + o] = acc;
            }
        } else {
            if (tid < 6) {
                int o = tid;
                float acc = bias[o];
                for (int i = 0; i < 64; i++)
                    acc = fmaf(d_hr[m*64 + i], W[o*64 + i], acc);
                outbuf[m*6 + o] = acc;
            }
        }
    }
}

// ---------------- kernel B: k-split tiled GEMM, 128x64 tile, 8x4 micro-tile --------------
// Ktot is always divisible by 32 (4224 or 4096): no k bounds checks.
__global__ void __launch_bounds__(256) convB_kernel(
    int layer, int Ktot, int co, int ow, int outsel, float* __restrict__ dout)
{
    __shared__ float sA[CB_BK][132];   // [k][m], 128 + 4 pad
    __shared__ float sB[CB_BK][64];    // [k][o]
    const float* K2l = d_K2 + layer*K2STRIDE;
    float* outbuf = (outsel==0) ? d_bufA : (outsel==1) ? d_bufB : dout;

    int m0 = blockIdx.x * 128;
    int tid = threadIdx.x;
    int nchunks = Ktot / CB_BK;

    // A-load: thread loads 16 consecutive k for one m row
    int mA = tid & 127;
    int kA = (tid >> 7) * 16;
    const float* tbase = d_t + (size_t)(m0 + mA) * Ktot;
    // B-load: thread loads 8 consecutive o for one k row
    int kB = tid >> 3;
    int oB = (tid & 7) * 8;

    int tx = (tid & 15) * 4;     // o
    int ty = (tid >> 4) * 8;     // m

    float acc[32];
    #pragma unroll
    for (int j = 0; j < 32; j++) acc[j] = 0.0f;

    float ra[16], rb[8];

    int c = blockIdx.y;
    if (c >= nchunks) return;
    {
        int kb = c * CB_BK;
        const float* ap = tbase + kb + kA;
        #pragma unroll
        for (int q = 0; q < 4; q++) {
            float4 vv = *(const float4*)(ap + q*4);
            ra[q*4+0]=vv.x; ra[q*4+1]=vv.y; ra[q*4+2]=vv.z; ra[q*4+3]=vv.w;
        }
        int kg = kb + kB;
        if (co == 64) {
            const float* bp = K2l + (size_t)kg*64 + oB;
            float4 v0 = *(const float4*)bp;
            float4 v1 = *(const float4*)(bp + 4);
            rb[0]=v0.x; rb[1]=v0.y; rb[2]=v0.z; rb[3]=v0.w;
            rb[4]=v1.x; rb[5]=v1.y; rb[6]=v1.z; rb[7]=v1.w;
        } else {
            #pragma unroll
            for (int j = 0; j < 8; j++)
                rb[j] = ((oB + j) < co) ? K2l[(size_t)kg*co + oB + j] : 0.0f;
        }
    }

    while (c < nchunks) {
        #pragma unroll
        for (int j = 0; j < 16; j++) sA[kA + j][mA] = ra[j];
        #pragma unroll
        for (int j = 0; j < 8; j++) sB[kB][oB + j] = rb[j];
        __syncthreads();

        int cn = c + CB_NKS;
        if (cn < nchunks) {
            int kb = cn * CB_BK;
            const float* ap = tbase + kb + kA;
            #pragma unroll
            for (int q = 0; q < 4; q++) {
                float4 vv = *(const float4*)(ap + q*4);
                ra[q*4+0]=vv.x; ra[q*4+1]=vv.y; ra[q*4+2]=vv.z; ra[q*4+3]=vv.w;
            }
            int kg = kb + kB;
            if (co == 64) {
                const float* bp = K2l + (size_t)kg*64 + oB;
                float4 v0 = *(const float4*)bp;
                float4 v1 = *(const float4*)(bp + 4);
                rb[0]=v0.x; rb[1]=v0.y; rb[2]=v0.z; rb[3]=v0.w;
                rb[4]=v1.x; rb[5]=v1.y; rb[6]=v1.z; rb[7]=v1.w;
            } else {
                #pragma unroll
                for (int j = 0; j < 8; j++)
                    rb[j] = ((oB + j) < co) ? K2l[(size_t)kg*co + oB + j] : 0.0f;
            }
        }

        #pragma unroll
        for (int k = 0; k < CB_BK; k++) {
            float4 b4 = *(const float4*)&sB[k][tx];
            float4 a0 = *(const float4*)&sA[k][ty];
            float4 a1 = *(const float4*)&sA[k][ty + 4];
            acc[ 0] = fmaf(a0.x, b4.x, acc[ 0]);
            acc[ 1] = fmaf(a0.x, b4.y, acc[ 1]);
            acc[ 2] = fmaf(a0.x, b4.z, acc[ 2]);
            acc[ 3] = fmaf(a0.x, b4.w, acc[ 3]);
            acc[ 4] = fmaf(a0.y, b4.x, acc[ 4]);
            acc[ 5] = fmaf(a0.y, b4.y, acc[ 5]);
            acc[ 6] = fmaf(a0.y, b4.z, acc[ 6]);
            acc[ 7] = fmaf(a0.y, b4.w, acc[ 7]);
            acc[ 8] = fmaf(a0.z, b4.x, acc[ 8]);
            acc[ 9] = fmaf(a0.z, b4.y, acc[ 9]);
            acc[10] = fmaf(a0.z, b4.z, acc[10]);
            acc[11] = fmaf(a0.z, b4.w, acc[11]);
            acc[12] = fmaf(a0.w, b4.x, acc[12]);
            acc[13] = fmaf(a0.w, b4.y, acc[13]);
            acc[14] = fmaf(a0.w, b4.z, acc[14]);
            acc[15] = fmaf(a0.w, b4.w, acc[15]);
            acc[16] = fmaf(a1.x, b4.x, acc[16]);
            acc[17] = fmaf(a1.x, b4.y, acc[17]);
            acc[18] = fmaf(a1.x, b4.z, acc[18]);
            acc[19] = fmaf(a1.x, b4.w, acc[19]);
            acc[20] = fmaf(a1.y, b4.x, acc[20]);
            acc[21] = fmaf(a1.y, b4.y, acc[21]);
            acc[22] = fmaf(a1.y, b4.z, acc[22]);
            acc[23] = fmaf(a1.y, b4.w, acc[23]);
            acc[24] = fmaf(a1.z, b4.x, acc[24]);
            acc[25] = fmaf(a1.z, b4.y, acc[25]);
            acc[26] = fmaf(a1.z, b4.z, acc[26]);
            acc[27] = fmaf(a1.z, b4.w, acc[27]);
            acc[28] = fmaf(a1.w, b4.x, acc[28]);
            acc[29] = fmaf(a1.w, b4.y, acc[29]);
            acc[30] = fmaf(a1.w, b4.z, acc[30]);
            acc[31] = fmaf(a1.w, b4.w, acc[31]);
        }
        __syncthreads();
        c = cn;
    }

    #pragma unroll
    for (int r = 0; r < 8; r++) {
        int m = m0 + ty + r;
        #pragma unroll
        for (int cc = 0; cc < 4; cc++) {
            int o = tx + cc;
            if (o < co) atomicAdd(outbuf + (size_t)m*ow + o, acc[r*4 + cc]);
        }
    }
}

// ---------------- host ----------------
extern "C" void kernel_launch(void* const* d_in, const int* in_sizes, int n_in,
                              void* d_out, int out_size)
{
    const float* p     = (const float*)d_in[0];
    const float* v     = (const float*)d_in[1];
    const float* other = (const float*)d_in[2];
    const float* mask  = (const float*)d_in[3];
    const float* kf    = (const float*)d_in[4];
    const float* Wf    = (const float*)d_in[5];
    const float* bf    = (const float*)d_in[6];
    const float* k1    = (const float*)d_in[7];
    const float* W1    = (const float*)d_in[8];
    const float* b1    = (const float*)d_in[9];
    const float* k2    = (const float*)d_in[10];
    const float* W2    = (const float*)d_in[11];
    const float* b2    = (const float*)d_in[12];
    const float* k3    = (const float*)d_in[13];
    const float* W3    = (const float*)d_in[14];
    const float* b3    = (const float*)d_in[15];
    const float* k4    = (const float*)d_in[16];
    const float* W4    = (const float*)d_in[17];
    const float* b4    = (const float*)d_in[18];
    float* out = (float*)d_out;

    prep_kernel<<<dim3(64,6), 256>>>(v, other, kf, k1, k2, k3, k4);          // 0
    geom_kernel<<<NP, 256>>>(p, mask);                                        // 1

    // layer 0: feats0 -> bufA
    convA_t<66,68,0><<<dim3(NP,4), 256>>>(Wf, bf, 0, out, 0, -1);             // 2
    convB_kernel<<<dim3(4, CB_NKS), 256>>>(0, 4224, 32, 64, 0, out);          // 3
    relu_kernel<<<128, 256>>>(0);                                             // 4

    // layer 1: d_hr -> bufB (resid bufA)
    convA_t<64,64,1><<<dim3(NP,4), 256>>>(W1, b1, 1, out, 1, 0);              // 5
    convB_kernel<<<dim3(4, CB_NKS), 256>>>(1, 4096, 64, 64, 1, out);
    relu_kernel<<<128, 256>>>(1);

    // layer 2: d_hr -> bufA (resid bufB)
    convA_t<64,64,1><<<dim3(NP,4), 256>>>(W2, b2, 0, out, 1, 1);
    convB_kernel<<<dim3(4, CB_NKS), 256>>>(2, 4096, 64, 64, 0, out);
    relu_kernel<<<128, 256>>>(0);

    // layer 3: d_hr -> bufB (resid bufA)
    convA_t<64,64,1><<<dim3(NP,4), 256>>>(W3, b3, 1, out, 1, 0);
    convB_kernel<<<dim3(4, CB_NKS), 256>>>(3, 4096, 64, 64, 1, out);
    relu_kernel<<<128, 256>>>(1);

    // layer 4: d_hr -> d_out, co=6, no residual
    convA_t<64,64,1><<<dim3(NP,4), 256>>>(W4, b4, 2, out, 2, -1);
    convB_kernel<<<dim3(4, CB_NKS), 256>>>(4, 4096, 6, 6, 2, out);
}